// round 15
// baseline (speedup 1.0000x reference)
#include <cuda_runtime.h>
#include <cuda_bf16.h>
#include <cstdint>
#include <math_constants.h>

// ---------------- problem constants ----------------
#define NQ      65536
#define DIMV    256
#define KCODES  1024
#define SPAT    16384
#define NTOT    16777216

// ---------------- device scratch ----------------
__device__ __nv_bfloat16 g_A[(size_t)NQ * 256];     // z_hi only (screening GEMM input)
__device__ float g_Zr[(size_t)NQ * DIMV];           // row-major fp32 z (exact)
__device__ __nv_bfloat16 g_E[KCODES * 256];         // e_hi
__device__ float g_heq2[KCODES];
__device__ int   g_cand[NQ * 8];                    // top-8 candidate codes per row
__device__ float g_cval[NQ * 8];                    // their approx scores (sorted desc)
__device__ int   g_idx[NQ];
__device__ int   g_cnt[KCODES];
__device__ int   g_off[KCODES];
__device__ int   g_cur[KCODES];
__device__ int   g_rows[NQ];
__device__ float g_invc[KCODES];
__device__ float g_newembed[KCODES * DIMV];
__device__ float g_zsq;
__device__ float g_l2;

// ---------------- PTX helpers (base sm_100 legal) ----------------
__device__ __forceinline__ uint32_t smem_u32(const void* p) {
    uint32_t a;
    asm("{ .reg .u64 t; cvta.to.shared.u64 t, %1; cvt.u32.u64 %0, t; }" : "=r"(a) : "l"(p));
    return a;
}
#define SWZ(x) ((x) ^ (((x) >> 3) & 0x70))

__device__ __forceinline__ void cpasync16(uint32_t s, const void* g) {
    asm volatile("cp.async.cg.shared.global [%0], [%1], 16;" :: "r"(s), "l"(g));
}
__device__ __forceinline__ void cpcommit() { asm volatile("cp.async.commit_group;"); }
__device__ __forceinline__ void cpwait1()  { asm volatile("cp.async.wait_group 1;" ::: "memory"); }

__device__ __forceinline__ void ldsm4(uint32_t* r, uint32_t a) {
    asm volatile("ldmatrix.sync.aligned.m8n8.x4.shared.b16 {%0,%1,%2,%3}, [%4];"
        : "=r"(r[0]), "=r"(r[1]), "=r"(r[2]), "=r"(r[3]) : "r"(a));
}
__device__ __forceinline__ void mma16816(float* c, const uint32_t* a, uint32_t b0, uint32_t b1) {
    asm volatile("mma.sync.aligned.m16n8k16.row.col.f32.bf16.bf16.f32 "
        "{%0,%1,%2,%3}, {%4,%5,%6,%7}, {%8,%9}, {%0,%1,%2,%3};"
        : "+f"(c[0]), "+f"(c[1]), "+f"(c[2]), "+f"(c[3])
        : "r"(a[0]), "r"(a[1]), "r"(a[2]), "r"(a[3]), "r"(b0), "r"(b1));
}

// sorted-desc top-4 insertion
__device__ __forceinline__ void ins4(float* tv, int* ti, float v, int c) {
    if (v <= tv[3]) return;
    if (v > tv[0]) {
        tv[3]=tv[2]; ti[3]=ti[2]; tv[2]=tv[1]; ti[2]=ti[1];
        tv[1]=tv[0]; ti[1]=ti[0]; tv[0]=v; ti[0]=c;
    } else if (v > tv[1]) {
        tv[3]=tv[2]; ti[3]=ti[2]; tv[2]=tv[1]; ti[2]=ti[1]; tv[1]=v; ti[1]=c;
    } else if (v > tv[2]) {
        tv[3]=tv[2]; ti[3]=ti[2]; tv[2]=v; ti[2]=c;
    } else { tv[3]=v; ti[3]=c; }
}
// sorted-desc top-8 insertion (bubble)
__device__ __forceinline__ void ins8(float* bv, int* bi, float v, int c) {
    if (v <= bv[7]) return;
    bv[7] = v; bi[7] = c;
    #pragma unroll
    for (int j = 7; j > 0; --j) {
        if (bv[j] > bv[j-1]) {
            float tf = bv[j]; bv[j] = bv[j-1]; bv[j-1] = tf;
            int   ii = bi[j]; bi[j] = bi[j-1]; bi[j-1] = ii;
        } else break;
    }
}

// ---------------- k_prep: build E (e_hi), heq2, zero counters ----------------
__global__ void k_prep(const float* __restrict__ embed) {
    __shared__ float ws[8];
    int k = blockIdx.x, c = threadIdx.x, lane = c & 31, w = c >> 5;
    float e = embed[k * DIMV + c];
    g_E[k * 256 + c] = __float2bfloat16(e);
    float s = e * e;
    #pragma unroll
    for (int o = 16; o; o >>= 1) s += __shfl_xor_sync(0xFFFFFFFFu, s, o);
    if (lane == 0) ws[w] = s;
    __syncthreads();
    if (c == 0) {
        float t = 0;
        #pragma unroll
        for (int i = 0; i < 8; ++i) t += ws[i];
        g_heq2[k] = 0.5f * t;
        g_cnt[k] = 0;
        if (k == 0) { g_zsq = 0.0f; g_l2 = 0.0f; }
    }
}

// ---------------- k_split: transpose z -> bf16 hi + fp32 row copy + sum(z^2) ----------------
__global__ void k_split(const float* __restrict__ z) {
    __shared__ float tile[32][33];
    __shared__ float ws[8];
    int s0 = blockIdx.x * 32, c0 = blockIdx.y * 32, b = blockIdx.z;
    int t = threadIdx.x, lane = t & 31, w = t >> 5;
    const float* zb = z + ((size_t)b * DIMV + c0) * SPAT + s0;
    float zsq = 0.0f;
    int si = t & 31, cb = t >> 5;
    #pragma unroll
    for (int i = 0; i < 4; ++i) {
        int c = cb + 8 * i;
        float v = zb[(size_t)c * SPAT + si];
        tile[c][si] = v;
        zsq += v * v;
    }
    __syncthreads();
    int ci = t & 31, rb = t >> 5;
    #pragma unroll
    for (int i = 0; i < 4; ++i) {
        int r = rb + 8 * i;
        float v = tile[ci][r];
        size_t n = (size_t)b * SPAT + s0 + r;
        g_A[n * 256 + c0 + ci] = __float2bfloat16(v);
        g_Zr[n * DIMV + c0 + ci] = v;
    }
    #pragma unroll
    for (int o = 16; o; o >>= 1) zsq += __shfl_xor_sync(0xFFFFFFFFu, zsq, o);
    if (lane == 0) ws[w] = zsq;
    __syncthreads();
    if (t == 0) {
        float s = 0;
        #pragma unroll
        for (int i = 0; i < 8; ++i) s += ws[i];
        atomicAdd(&g_zsq, s);
    }
}

// ---------------- k_dummy: spacer so k_mma is the 4th launch (ncu capture slot) ----------------
__global__ void k_dummy() {}

// ---------------- k_mma: K=256 HMMA screen, M=32/CTA, 3 CTAs/SM, top-4/slot ----------------
#define SM_A    0                       // 4 chunks x 4096 = 16384
#define SM_B    16384                   // 3 x 16384 = 49152 -> 65536
#define SM_HQ   65536                   // 4096 -> 69632
#define SM_END  69632
#define SM_SZ2  (SM_END + 1024)
// staging scv/sci overlays the B ring after the mainloop (16 KB needed, 48 KB available)

__global__ __launch_bounds__(256, 3) void k_mma() {
    extern __shared__ char smraw[];
    uint32_t base0 = smem_u32(smraw);
    uint32_t sb = (base0 + 1023u) & ~1023u;
    char* sp = smraw + (sb - base0);
    const uint32_t A = sb + SM_A, B = sb + SM_B;
    float* heqs = (float*)(sp + SM_HQ);
    float* scv  = (float*)(sp + SM_B);           // overlay (post-mainloop): 32*64*4 = 8192
    int*   sci  = (int*)(sp + SM_B + 8192);      // overlay (post-mainloop): 8192

    const int t = threadIdx.x, lane = t & 31, w = t >> 5;
    const int warp_m = w >> 2, warp_n = w & 3;   // 2 x 16 rows, 4 x 32 cols
    const int n0 = blockIdx.x * 32;

    #pragma unroll
    for (int i = 0; i < 4; ++i) heqs[t + 256 * i] = g_heq2[t + 256 * i];

    // per-thread cp.async offsets for a [128][64] B chunk (computed once)
    uint32_t sm_off[4], gl_off[4];
    #pragma unroll
    for (int j = 0; j < 4; ++j) {
        int seg = t + 256 * j;          // 1024 16B segments
        int r = seg >> 3, g8 = seg & 7;
        sm_off[j] = SWZ((uint32_t)(r * 128 + g8 * 16));
        gl_off[j] = (uint32_t)(r * 256 + g8 * 8);   // elements
    }

    // A tile: 32 rows x 256 bf16 as 4 chunks [32][64] (4KB each), SW128-swizzled
    const __nv_bfloat16* Ag = g_A + (size_t)n0 * 256;
    #pragma unroll
    for (int j = 0; j < 4; ++j) {
        int i = t + 256 * j;            // 1024 16B segments
        int r = i >> 5, g = i & 31;
        int chunk = g >> 3, g8 = g & 7;
        cpasync16(A + chunk * 4096 + SWZ(r * 128 + g8 * 16), Ag + (size_t)r * 256 + g * 8);
    }
    cpcommit();
    // B prologue: chunks 0,1 into buffers 0,1 (prefetch distance 2, 3 buffers)
    #pragma unroll
    for (int g = 0; g < 2; ++g) {
        const __nv_bfloat16* Eg = g_E + g * 64;
        #pragma unroll
        for (int j = 0; j < 4; ++j)
            cpasync16(B + g * 16384 + sm_off[j], Eg + gl_off[j]);
        cpcommit();
    }

    // LDSM offsets (chunk/buffer-relative, loop-invariant)
    uint32_t a_off[4];
    {
        int ar = warp_m * 16 + (lane & 15);
        uint32_t asw = (uint32_t)((ar & 7) << 4);
        #pragma unroll
        for (int ks = 0; ks < 4; ++ks)
            a_off[ks] = (uint32_t)(ar * 128)
                      + (((uint32_t)(ks * 32 + ((lane >> 4) * 16))) ^ asw);
    }
    const int sel = lane >> 3;
    uint32_t b_off[2][4];
    #pragma unroll
    for (int ntp = 0; ntp < 2; ++ntp) {
        int brow = warp_n * 32 + ntp * 16 + (sel >> 1) * 8 + (lane & 7);
        #pragma unroll
        for (int ks = 0; ks < 4; ++ks)
            b_off[ntp][ks] = (uint32_t)(brow * 128)
                           + (((uint32_t)(ks * 32 + (sel & 1) * 16)) ^ ((uint32_t)((brow & 7) << 4)));
    }

    float acc[4][4];                     // warp tile 16 x 32: [ntp*2 + j]
    float tv[2][4];                      // 2 row-slots x top-4
    int   ti[2][4];
    #pragma unroll
    for (int s = 0; s < 2; ++s)
        #pragma unroll
        for (int j = 0; j < 4; ++j) { tv[s][j] = -CUDART_INF_F; ti[s][j] = 0; }
    const int cbth = warp_n * 32 + 2 * (lane & 3);   // per-thread col base within chunk

    for (int g = 0; g < 32; ++g) {
        const int nt = g >> 2, h = g & 3;
        const int cur = g % 3;
        cpwait1();
        __syncthreads();

        // prefetch chunk g+2 into buffer (g+2)%3 (consumed at g-1; safe after sync)
        if (g + 2 < 32) {
            int gn = g + 2;
            const __nv_bfloat16* Eg = g_E + (size_t)((gn >> 2) * 128) * 256 + (gn & 3) * 64;
            uint32_t bb = B + (gn % 3) * 16384;
            #pragma unroll
            for (int j = 0; j < 4; ++j)
                cpasync16(bb + sm_off[j], Eg + gl_off[j]);
        }
        cpcommit();

        if (h == 0) {
            #pragma unroll
            for (int nti = 0; nti < 4; ++nti)
                #pragma unroll
                for (int q = 0; q < 4; ++q) acc[nti][q] = 0.0f;
        }

        // gemm: A chunk h, B buffer cur
        {
            const uint32_t Ab = A + h * 4096;
            const uint32_t Bb = B + cur * 16384;
            #pragma unroll
            for (int ks = 0; ks < 4; ++ks) {
                uint32_t af[4];
                ldsm4(af, Ab + a_off[ks]);
                uint32_t bfg[2][4];
                ldsm4(bfg[0], Bb + b_off[0][ks]);
                ldsm4(bfg[1], Bb + b_off[1][ks]);
                #pragma unroll
                for (int ntp = 0; ntp < 2; ++ntp)
                    #pragma unroll
                    for (int j = 0; j < 2; ++j)
                        mma16816(acc[ntp * 2 + j], af, bfg[ntp][2 * j], bfg[ntp][2 * j + 1]);
            }
        }

        if (h == 3) {
            int cb = nt * 128 + cbth;
            #pragma unroll
            for (int nti2 = 0; nti2 < 4; ++nti2) {
                int code0 = cb + nti2 * 8;
                float h0 = heqs[code0], h1 = heqs[code0 + 1];
                const float* a = acc[nti2];
                ins4(tv[0], ti[0], a[0] - h0, code0);
                ins4(tv[0], ti[0], a[1] - h1, code0 + 1);
                ins4(tv[1], ti[1], a[2] - h0, code0);
                ins4(tv[1], ti[1], a[3] - h1, code0 + 1);
            }
        }
    }

    // all B reads done; overlay staging onto the B ring (64 entries per row)
    __syncthreads();
    #pragma unroll
    for (int s = 0; s < 2; ++s) {
        int row = warp_m * 16 + s * 8 + (lane >> 2);
        int col = warp_n * 16 + (lane & 3) * 4;
        #pragma unroll
        for (int j = 0; j < 4; ++j) {
            scv[row * 64 + col + j] = tv[s][j];
            sci[row * 64 + col + j] = ti[s][j];
        }
    }
    __syncthreads();
    if (t < 32) {
        float bv[8]; int bi[8];
        #pragma unroll
        for (int j = 0; j < 8; ++j) { bv[j] = -CUDART_INF_F; bi[j] = 0; }
        #pragma unroll 4
        for (int i = 0; i < 64; ++i) ins8(bv, bi, scv[t * 64 + i], sci[t * 64 + i]);
        #pragma unroll
        for (int j = 0; j < 8; ++j) {
            g_cand[(size_t)(n0 + t) * 8 + j] = bi[j];
            g_cval[(size_t)(n0 + t) * 8 + j] = bv[j];
        }
    }
}

// ---------------- k_rescore: gated exact fp32 + fp64 near-tie verify ----------------
__global__ __launch_bounds__(256) void k_rescore(const float* __restrict__ embed) {
    int t = threadIdx.x, lane = t & 31, w = t >> 5;
    int r = blockIdx.x * 8 + w;

    const float4* zp = (const float4*)(g_Zr + (size_t)r * DIMV + lane * 8);
    float4 z0 = zp[0], z1 = zp[1];
    float zv[8] = { z0.x, z0.y, z0.z, z0.w, z1.x, z1.y, z1.z, z1.w };

    int   ck[8];
    float cv[8];
    #pragma unroll
    for (int j = 0; j < 8; ++j) {
        ck[j] = g_cand[(size_t)r * 8 + j];
        cv[j] = g_cval[(size_t)r * 8 + j];
    }
    const float thr = cv[0] - 0.01f;     // 7-sigma screening-noise window

    float best = -CUDART_INF_F, second = -CUDART_INF_F;
    int bidx = 0x7FFFFFFF;
    float sc[8];
    #pragma unroll
    for (int c = 0; c < 8; ++c) sc[c] = -CUDART_INF_F;

    for (int c = 0; c < 8; ++c) {
        if (cv[c] < thr) break;          // sorted desc: rest are worse
        int k = ck[c];
        const float4* ep = (const float4*)(embed + (size_t)k * DIMV + lane * 8);
        float4 e0 = ep[0], e1 = ep[1];
        float p = zv[0] * e0.x + zv[1] * e0.y + zv[2] * e0.z + zv[3] * e0.w
                + zv[4] * e1.x + zv[5] * e1.y + zv[6] * e1.z + zv[7] * e1.w;
        #pragma unroll
        for (int o = 16; o; o >>= 1) p += __shfl_xor_sync(0xFFFFFFFFu, p, o);
        float s = p - g_heq2[k];
        sc[c] = s;
        if (s > best || (s == best && k < bidx)) { second = best; best = s; bidx = k; }
        else if (s > second) second = s;
    }

    if (best - second < 1e-3f) {
        double dbest = -CUDART_INF;
        int dbidx = 0x7FFFFFFF;
        for (int c = 0; c < 8; ++c) {
            if (sc[c] < best - 2e-3f) continue;    // only genuine near-ties
            int k = ck[c];
            const float4* ep = (const float4*)(embed + (size_t)k * DIMV + lane * 8);
            float4 e0 = ep[0], e1 = ep[1];
            double acc = 0.0, e2 = 0.0;
            double ev[8] = { e0.x, e0.y, e0.z, e0.w, e1.x, e1.y, e1.z, e1.w };
            #pragma unroll
            for (int j = 0; j < 8; ++j) {
                acc += (double)zv[j] * ev[j];
                e2  += ev[j] * ev[j];
            }
            double s2 = acc - 0.5 * e2;
            #pragma unroll
            for (int o = 16; o; o >>= 1) s2 += __shfl_xor_sync(0xFFFFFFFFu, s2, o);
            if (s2 > dbest || (s2 == dbest && k < dbidx)) { dbest = s2; dbidx = k; }
        }
        bidx = dbidx;
    }

    if (lane == 0) {
        g_idx[r] = bidx;
        atomicAdd(&g_cnt[bidx], 1);
    }
}

// ---------------- k_scan: EMA sizes + invc + exclusive prefix of counts ----------------
__global__ void k_scan(const float* __restrict__ ema_cs) {
    __shared__ float red[KCODES];
    __shared__ int sc[KCODES];
    int t = threadIdx.x;
    int c = g_cnt[t];
    float ncs = 0.99f * ema_cs[t] + 0.01f * (float)c;
    red[t] = ncs; sc[t] = c;
    __syncthreads();
    for (int s = 512; s > 0; s >>= 1) { if (t < s) red[t] += red[t + s]; __syncthreads(); }
    float n = red[0];
    for (int off = 1; off < KCODES; off <<= 1) {
        int v = (t >= off) ? sc[t - off] : 0;
        __syncthreads();
        sc[t] += v;
        __syncthreads();
    }
    int excl = sc[t] - c;
    g_off[t] = excl; g_cur[t] = excl;
    float cl = (ncs + 1e-5f) / (n + KCODES * 1e-5f) * n;
    g_invc[t] = 1.0f / cl;
}

// ---------------- k_bucket ----------------
__global__ void k_bucket() {
    int n = blockIdx.x * 256 + threadIdx.x;
    int k = g_idx[n];
    int p = atomicAdd(&g_cur[k], 1);
    g_rows[p] = n;
}

// ---------------- k_esum: per-code fp32 sum + new codebook + loss terms ----------------
__global__ void k_esum(const float* __restrict__ ema_es) {
    __shared__ float ws[8];
    int k = blockIdx.x, c = threadIdx.x, lane = c & 31, w = c >> 5;
    int off = g_off[k], cnt = g_cnt[k];
    float acc = 0.0f;
    for (int i = 0; i < cnt; ++i) {
        int n = g_rows[off + i];
        acc += g_Zr[(size_t)n * DIMV + c];
    }
    float newe = (0.99f * ema_es[k * DIMV + c] + 0.01f * acc) * g_invc[k];
    g_newembed[k * DIMV + c] = newe;
    float part = (float)cnt * newe * newe - 2.0f * acc * newe;
    #pragma unroll
    for (int o = 16; o; o >>= 1) part += __shfl_xor_sync(0xFFFFFFFFu, part, o);
    if (lane == 0) ws[w] = part;
    __syncthreads();
    if (c == 0) {
        float s = 0;
        #pragma unroll
        for (int i = 0; i < 8; ++i) s += ws[i];
        atomicAdd(&g_l2, s);
    }
}

// ---------------- k_gather: write z_q (transposed), indices, loss ----------------
__global__ void k_gather(float* __restrict__ out) {
    __shared__ float stg[DIMV * 33];
    __shared__ int sk[32];
    int t = threadIdx.x;
    int n0 = blockIdx.x * 32;
    int b = n0 >> 14, s0 = n0 & (SPAT - 1);
    if (t < 32) {
        int k = g_idx[n0 + t];
        sk[t] = k;
        out[NTOT + 1 + n0 + t] = (float)k;
    }
    __syncthreads();
    #pragma unroll 4
    for (int i = 0; i < 32; ++i)
        stg[t * 33 + i] = g_newembed[sk[i] * DIMV + t];
    __syncthreads();
    float* ob = out + (size_t)b * (DIMV * SPAT) + s0;
    #pragma unroll 4
    for (int i = 0; i < 32; ++i) {
        int j = t + 256 * i;
        int c = j >> 5, r = j & 31;
        ob[(size_t)c * SPAT + r] = stg[c * 33 + r];
    }
    if (blockIdx.x == 0 && t == 0)
        out[NTOT] = 0.25f * (g_zsq + g_l2) * (1.0f / 16777216.0f);
}

// ---------------- launch ----------------
extern "C" void kernel_launch(void* const* d_in, const int* in_sizes, int n_in,
                              void* d_out, int out_size) {
    const float* z      = (const float*)d_in[0];
    const float* embed  = (const float*)d_in[1];
    const float* ema_cs = (const float*)d_in[2];
    const float* ema_es = (const float*)d_in[3];
    float* out = (float*)d_out;

    static bool init = false;
    if (!init) {
        cudaFuncSetAttribute(k_mma, cudaFuncAttributeMaxDynamicSharedMemorySize, SM_SZ2);
        init = true;
    }

    k_prep<<<KCODES, 256>>>(embed);
    k_split<<<dim3(512, 8, 4), 256>>>(z);
    k_dummy<<<1, 32>>>();
    k_mma<<<2048, 256, SM_SZ2>>>();
    k_rescore<<<8192, 256>>>(embed);
    k_scan<<<1, 1024>>>(ema_cs);
    k_bucket<<<256, 256>>>();
    k_esum<<<KCODES, 256>>>(ema_es);
    k_gather<<<2048, 256>>>(out);
}

// round 16
// speedup vs baseline: 1.1271x; 1.1271x over previous
#include <cuda_runtime.h>
#include <cuda_bf16.h>
#include <cstdint>
#include <math_constants.h>

// ---------------- problem constants ----------------
#define NQ      65536
#define DIMV    256
#define KCODES  1024
#define SPAT    16384
#define NTOT    16777216

// ---------------- device scratch ----------------
__device__ __nv_bfloat16 g_A[(size_t)NQ * 256];     // z_hi only (screening GEMM input)
__device__ float g_Zr[(size_t)NQ * DIMV];           // row-major fp32 z (exact)
__device__ __nv_bfloat16 g_E[KCODES * 256];         // e_hi
__device__ float g_heq2[KCODES];
__device__ int   g_cand[NQ * 8];                    // top-8 candidate codes per row
__device__ float g_cval[NQ * 8];                    // approx scores; [1]=+INF marks decided
__device__ int   g_idx[NQ];
__device__ int   g_cnt[KCODES];
__device__ int   g_off[KCODES];
__device__ int   g_cur[KCODES];
__device__ int   g_rows[NQ];
__device__ float g_invc[KCODES];
__device__ float g_newembed[KCODES * DIMV];
__device__ float g_zsq;
__device__ float g_l2;

// ---------------- PTX helpers (base sm_100 legal) ----------------
__device__ __forceinline__ uint32_t smem_u32(const void* p) {
    uint32_t a;
    asm("{ .reg .u64 t; cvta.to.shared.u64 t, %1; cvt.u32.u64 %0, t; }" : "=r"(a) : "l"(p));
    return a;
}
#define SWZ(x) ((x) ^ (((x) >> 3) & 0x70))

__device__ __forceinline__ void cpasync16(uint32_t s, const void* g) {
    asm volatile("cp.async.cg.shared.global [%0], [%1], 16;" :: "r"(s), "l"(g));
}
__device__ __forceinline__ void cpcommit() { asm volatile("cp.async.commit_group;"); }
__device__ __forceinline__ void cpwait2()  { asm volatile("cp.async.wait_group 2;" ::: "memory"); }

__device__ __forceinline__ void ldsm4(uint32_t* r, uint32_t a) {
    asm volatile("ldmatrix.sync.aligned.m8n8.x4.shared.b16 {%0,%1,%2,%3}, [%4];"
        : "=r"(r[0]), "=r"(r[1]), "=r"(r[2]), "=r"(r[3]) : "r"(a));
}
__device__ __forceinline__ void mma16816(float* c, const uint32_t* a, uint32_t b0, uint32_t b1) {
    asm volatile("mma.sync.aligned.m16n8k16.row.col.f32.bf16.bf16.f32 "
        "{%0,%1,%2,%3}, {%4,%5,%6,%7}, {%8,%9}, {%0,%1,%2,%3};"
        : "+f"(c[0]), "+f"(c[1]), "+f"(c[2]), "+f"(c[3])
        : "r"(a[0]), "r"(a[1]), "r"(a[2]), "r"(a[3]), "r"(b0), "r"(b1));
}

// sorted-desc top-4 insertion
__device__ __forceinline__ void ins4(float* tv, int* ti, float v, int c) {
    if (v <= tv[3]) return;
    if (v > tv[0]) {
        tv[3]=tv[2]; ti[3]=ti[2]; tv[2]=tv[1]; ti[2]=ti[1];
        tv[1]=tv[0]; ti[1]=ti[0]; tv[0]=v; ti[0]=c;
    } else if (v > tv[1]) {
        tv[3]=tv[2]; ti[3]=ti[2]; tv[2]=tv[1]; ti[2]=ti[1]; tv[1]=v; ti[1]=c;
    } else if (v > tv[2]) {
        tv[3]=tv[2]; ti[3]=ti[2]; tv[2]=v; ti[2]=c;
    } else { tv[3]=v; ti[3]=c; }
}
// sorted-desc top-8 insertion (bubble)
__device__ __forceinline__ void ins8(float* bv, int* bi, float v, int c) {
    if (v <= bv[7]) return;
    bv[7] = v; bi[7] = c;
    #pragma unroll
    for (int j = 7; j > 0; --j) {
        if (bv[j] > bv[j-1]) {
            float tf = bv[j]; bv[j] = bv[j-1]; bv[j-1] = tf;
            int   ii = bi[j]; bi[j] = bi[j-1]; bi[j-1] = ii;
        } else break;
    }
}

// ---------------- k_prep: build E (e_hi), heq2, zero counters ----------------
__global__ void k_prep(const float* __restrict__ embed) {
    __shared__ float ws[8];
    int k = blockIdx.x, c = threadIdx.x, lane = c & 31, w = c >> 5;
    float e = embed[k * DIMV + c];
    g_E[k * 256 + c] = __float2bfloat16(e);
    float s = e * e;
    #pragma unroll
    for (int o = 16; o; o >>= 1) s += __shfl_xor_sync(0xFFFFFFFFu, s, o);
    if (lane == 0) ws[w] = s;
    __syncthreads();
    if (c == 0) {
        float t = 0;
        #pragma unroll
        for (int i = 0; i < 8; ++i) t += ws[i];
        g_heq2[k] = 0.5f * t;
        g_cnt[k] = 0;
        if (k == 0) { g_zsq = 0.0f; g_l2 = 0.0f; }
    }
}

// ---------------- k_split: transpose z -> bf16 hi + fp32 row copy + sum(z^2) ----------------
__global__ void k_split(const float* __restrict__ z) {
    __shared__ float tile[32][33];
    __shared__ float ws[8];
    int s0 = blockIdx.x * 32, c0 = blockIdx.y * 32, b = blockIdx.z;
    int t = threadIdx.x, lane = t & 31, w = t >> 5;
    const float* zb = z + ((size_t)b * DIMV + c0) * SPAT + s0;
    float zsq = 0.0f;
    int si = t & 31, cb = t >> 5;
    #pragma unroll
    for (int i = 0; i < 4; ++i) {
        int c = cb + 8 * i;
        float v = zb[(size_t)c * SPAT + si];
        tile[c][si] = v;
        zsq += v * v;
    }
    __syncthreads();
    int ci = t & 31, rb = t >> 5;
    #pragma unroll
    for (int i = 0; i < 4; ++i) {
        int r = rb + 8 * i;
        float v = tile[ci][r];
        size_t n = (size_t)b * SPAT + s0 + r;
        g_A[n * 256 + c0 + ci] = __float2bfloat16(v);
        g_Zr[n * DIMV + c0 + ci] = v;
    }
    #pragma unroll
    for (int o = 16; o; o >>= 1) zsq += __shfl_xor_sync(0xFFFFFFFFu, zsq, o);
    if (lane == 0) ws[w] = zsq;
    __syncthreads();
    if (t == 0) {
        float s = 0;
        #pragma unroll
        for (int i = 0; i < 8; ++i) s += ws[i];
        atomicAdd(&g_zsq, s);
    }
}

// ---------------- k_dummy: spacer so k_mma is the 4th launch (ncu capture slot) ----------------
__global__ void k_dummy() {}

// ---------------- k_mma: K=256 HMMA screen (R11 config) + margin-gated finalize ----------------
#define SM_A    0                       // 4 chunks x 8192 = 32768
#define SM_B    32768                   // 4 x 16384 = 65536 -> 98304
#define SM_HQ   98304                   // 4096 -> 102400
#define SM_END  102400
#define SM_SZ2  (SM_END + 1024)
// staging scv/sci overlays the B ring after the mainloop (16 KB needed, 64 KB available)

__global__ __launch_bounds__(256, 2) void k_mma() {
    extern __shared__ char smraw[];
    uint32_t base0 = smem_u32(smraw);
    uint32_t sb = (base0 + 1023u) & ~1023u;
    char* sp = smraw + (sb - base0);
    const uint32_t A = sb + SM_A, B = sb + SM_B;
    float* heqs = (float*)(sp + SM_HQ);
    float* scv  = (float*)(sp + SM_B);           // overlay (post-mainloop)
    int*   sci  = (int*)(sp + SM_B + 8192);      // overlay (post-mainloop)

    const int t = threadIdx.x, lane = t & 31, w = t >> 5;
    const int warp_m = w >> 1, warp_n = w & 1;   // 4 x 16 rows, 2 x 64 cols
    const int n0 = blockIdx.x * 64;

    #pragma unroll
    for (int i = 0; i < 4; ++i) heqs[t + 256 * i] = g_heq2[t + 256 * i];

    // per-thread cp.async offsets for a [128][64] B chunk (computed once)
    uint32_t sm_off[4], gl_off[4];
    #pragma unroll
    for (int j = 0; j < 4; ++j) {
        int seg = t + 256 * j;          // 1024 16B segments
        int r = seg >> 3, g8 = seg & 7;
        sm_off[j] = SWZ((uint32_t)(r * 128 + g8 * 16));
        gl_off[j] = (uint32_t)(r * 256 + g8 * 8);   // elements
    }

    // A tile: 64 rows x 256 bf16 as 4 chunks [64][64] (8KB each), SW128-swizzled
    const __nv_bfloat16* Ag = g_A + (size_t)n0 * 256;
    #pragma unroll
    for (int j = 0; j < 8; ++j) {
        int i = t + 256 * j;            // 2048 16B segments
        int r = i >> 5, g = i & 31;
        int chunk = g >> 3, g8 = g & 7;
        cpasync16(A + chunk * 8192 + SWZ(r * 128 + g8 * 16), Ag + (size_t)r * 256 + g * 8);
    }
    cpcommit();
    // B prologue: chunks 0,1,2 into buffers 0,1,2
    #pragma unroll
    for (int g = 0; g < 3; ++g) {
        const __nv_bfloat16* Eg = g_E + g * 64;
        #pragma unroll
        for (int j = 0; j < 4; ++j)
            cpasync16(B + g * 16384 + sm_off[j], Eg + gl_off[j]);
        cpcommit();
    }

    // precomputed LDSM addresses (loop-invariant)
    const int arow = warp_m * 16 + (lane & 15);
    const uint32_t aswz = (uint32_t)((arow & 7) << 4);
    uint32_t a_addr[4][4];
    #pragma unroll
    for (int h = 0; h < 4; ++h)
        #pragma unroll
        for (int ks = 0; ks < 4; ++ks)
            a_addr[h][ks] = A + h * 8192 + arow * 128
                          + (((uint32_t)(ks * 32 + ((lane >> 4) * 16))) ^ aswz);
    const int sel = lane >> 3;
    uint32_t b_off[4][4];
    #pragma unroll
    for (int ntp = 0; ntp < 4; ++ntp) {
        int brow = warp_n * 64 + ntp * 16 + (sel >> 1) * 8 + (lane & 7);
        #pragma unroll
        for (int ks = 0; ks < 4; ++ks)
            b_off[ntp][ks] = (uint32_t)(brow * 128)
                           + (((uint32_t)(ks * 32 + (sel & 1) * 16)) ^ ((uint32_t)((brow & 7) << 4)));
    }

    float acc[8][4];                     // warp tile 16 x 64
    float tv[2][4];
    int   ti[2][4];
    #pragma unroll
    for (int s = 0; s < 2; ++s)
        #pragma unroll
        for (int j = 0; j < 4; ++j) { tv[s][j] = -CUDART_INF_F; ti[s][j] = 0; }

    for (int g = 0; g < 32; ++g) {
        const int nt = g >> 2, h = g & 3;
        cpwait2();
        __syncthreads();

        // prefetch chunk g+3 into buffer (g+3)&3 (consumed at g-1; safe after sync)
        if (g + 3 < 32) {
            int gn = g + 3;
            const __nv_bfloat16* Eg = g_E + (size_t)((gn >> 2) * 128) * 256 + (gn & 3) * 64;
            uint32_t bb = B + (gn & 3) * 16384;
            #pragma unroll
            for (int j = 0; j < 4; ++j)
                cpasync16(bb + sm_off[j], Eg + gl_off[j]);
        }
        cpcommit();

        if (h == 0) {
            #pragma unroll
            for (int nti = 0; nti < 8; ++nti)
                #pragma unroll
                for (int q = 0; q < 4; ++q) acc[nti][q] = 0.0f;
        }

        // gemm: A chunk h, B buffer g&3 (addresses precomputed)
        {
            const uint32_t Bb = B + (g & 3) * 16384;
            #pragma unroll
            for (int ks = 0; ks < 4; ++ks) {
                uint32_t af[4];
                ldsm4(af, a_addr[h][ks]);
                uint32_t bfg[4][4];
                #pragma unroll
                for (int ntp = 0; ntp < 4; ++ntp)
                    ldsm4(bfg[ntp], Bb + b_off[ntp][ks]);
                #pragma unroll
                for (int nti = 0; nti < 8; ++nti) {
                    int ntp = nti >> 1, pr = (nti & 1) * 2;
                    mma16816(acc[nti], af, bfg[ntp][pr], bfg[ntp][pr + 1]);
                }
            }
        }

        if (h == 3) {
            #pragma unroll
            for (int nti = 0; nti < 8; ++nti) {
                int code0 = nt * 128 + warp_n * 64 + nti * 8 + 2 * (lane & 3);
                float h0 = heqs[code0], h1 = heqs[code0 + 1];
                ins4(tv[0], ti[0], acc[nti][0] - h0, code0);
                ins4(tv[0], ti[0], acc[nti][1] - h1, code0 + 1);
                ins4(tv[1], ti[1], acc[nti][2] - h0, code0);
                ins4(tv[1], ti[1], acc[nti][3] - h1, code0 + 1);
            }
        }
    }

    // all B reads done; overlay staging onto the B ring
    __syncthreads();
    #pragma unroll
    for (int s = 0; s < 2; ++s) {
        int row = warp_m * 16 + s * 8 + (lane >> 2);
        int col = warp_n * 16 + (lane & 3) * 4;
        #pragma unroll
        for (int j = 0; j < 4; ++j) {
            scv[row * 32 + col + j] = tv[s][j];
            sci[row * 32 + col + j] = ti[s][j];
        }
    }
    __syncthreads();
    if (t < 64) {
        float bv[8]; int bi[8];
        #pragma unroll
        for (int j = 0; j < 8; ++j) { bv[j] = -CUDART_INF_F; bi[j] = 0; }
        #pragma unroll 4
        for (int i = 0; i < 32; ++i) ins8(bv, bi, scv[t * 32 + i], sci[t * 32 + i]);
        size_t base = (size_t)(n0 + t) * 8;
        if (bv[0] - bv[1] >= 0.03f) {
            // margin >> 30 sigma of screening noise: winner is exact; finalize here
            g_idx[n0 + t] = bi[0];
            atomicAdd(&g_cnt[bi[0]], 1);
            g_cand[base] = bi[0];
            g_cval[base] = bv[0];
            g_cval[base + 1] = __int_as_float(0x7f800000);   // +INF = decided marker
        } else {
            #pragma unroll
            for (int j = 0; j < 8; ++j) {
                g_cand[base + j] = bi[j];
                g_cval[base + j] = bv[j];
            }
        }
    }
}

// ---------------- k_rescore: skip decided rows; gated exact fp32 + fp64 verify ----------------
__global__ __launch_bounds__(256) void k_rescore(const float* __restrict__ embed) {
    int t = threadIdx.x, lane = t & 31, w = t >> 5;
    int r = blockIdx.x * 8 + w;

    // decided in k_mma? (broadcast 4B load before touching the 1KB z row)
    float cv1 = g_cval[(size_t)r * 8 + 1];
    if (cv1 == __int_as_float(0x7f800000)) return;

    const float4* zp = (const float4*)(g_Zr + (size_t)r * DIMV + lane * 8);
    float4 z0 = zp[0], z1 = zp[1];
    float zv[8] = { z0.x, z0.y, z0.z, z0.w, z1.x, z1.y, z1.z, z1.w };

    int   ck[8];
    float cv[8];
    #pragma unroll
    for (int j = 0; j < 8; ++j) {
        ck[j] = g_cand[(size_t)r * 8 + j];
        cv[j] = g_cval[(size_t)r * 8 + j];
    }
    const float thr = cv[0] - 0.01f;     // screening-noise window

    float best = -CUDART_INF_F, second = -CUDART_INF_F;
    int bidx = 0x7FFFFFFF;
    float sc[8];
    #pragma unroll
    for (int c = 0; c < 8; ++c) sc[c] = -CUDART_INF_F;

    for (int c = 0; c < 8; ++c) {
        if (cv[c] < thr) break;          // sorted desc: rest are worse
        int k = ck[c];
        const float4* ep = (const float4*)(embed + (size_t)k * DIMV + lane * 8);
        float4 e0 = ep[0], e1 = ep[1];
        float p = zv[0] * e0.x + zv[1] * e0.y + zv[2] * e0.z + zv[3] * e0.w
                + zv[4] * e1.x + zv[5] * e1.y + zv[6] * e1.z + zv[7] * e1.w;
        #pragma unroll
        for (int o = 16; o; o >>= 1) p += __shfl_xor_sync(0xFFFFFFFFu, p, o);
        float s = p - g_heq2[k];
        sc[c] = s;
        if (s > best || (s == best && k < bidx)) { second = best; best = s; bidx = k; }
        else if (s > second) second = s;
    }

    if (best - second < 1e-3f) {
        double dbest = -CUDART_INF;
        int dbidx = 0x7FFFFFFF;
        for (int c = 0; c < 8; ++c) {
            if (sc[c] < best - 2e-3f) continue;    // only genuine near-ties
            int k = ck[c];
            const float4* ep = (const float4*)(embed + (size_t)k * DIMV + lane * 8);
            float4 e0 = ep[0], e1 = ep[1];
            double acc = 0.0, e2 = 0.0;
            double ev[8] = { e0.x, e0.y, e0.z, e0.w, e1.x, e1.y, e1.z, e1.w };
            #pragma unroll
            for (int j = 0; j < 8; ++j) {
                acc += (double)zv[j] * ev[j];
                e2  += ev[j] * ev[j];
            }
            double s2 = acc - 0.5 * e2;
            #pragma unroll
            for (int o = 16; o; o >>= 1) s2 += __shfl_xor_sync(0xFFFFFFFFu, s2, o);
            if (s2 > dbest || (s2 == dbest && k < dbidx)) { dbest = s2; dbidx = k; }
        }
        bidx = dbidx;
    }

    if (lane == 0) {
        g_idx[r] = bidx;
        atomicAdd(&g_cnt[bidx], 1);
    }
}

// ---------------- k_scan: EMA sizes + invc + exclusive prefix of counts ----------------
__global__ void k_scan(const float* __restrict__ ema_cs) {
    __shared__ float red[KCODES];
    __shared__ int sc[KCODES];
    int t = threadIdx.x;
    int c = g_cnt[t];
    float ncs = 0.99f * ema_cs[t] + 0.01f * (float)c;
    red[t] = ncs; sc[t] = c;
    __syncthreads();
    for (int s = 512; s > 0; s >>= 1) { if (t < s) red[t] += red[t + s]; __syncthreads(); }
    float n = red[0];
    for (int off = 1; off < KCODES; off <<= 1) {
        int v = (t >= off) ? sc[t - off] : 0;
        __syncthreads();
        sc[t] += v;
        __syncthreads();
    }
    int excl = sc[t] - c;
    g_off[t] = excl; g_cur[t] = excl;
    float cl = (ncs + 1e-5f) / (n + KCODES * 1e-5f) * n;
    g_invc[t] = 1.0f / cl;
}

// ---------------- k_bucket ----------------
__global__ void k_bucket() {
    int n = blockIdx.x * 256 + threadIdx.x;
    int k = g_idx[n];
    int p = atomicAdd(&g_cur[k], 1);
    g_rows[p] = n;
}

// ---------------- k_esum: per-code fp32 sum + new codebook + loss terms ----------------
__global__ void k_esum(const float* __restrict__ ema_es) {
    __shared__ float ws[8];
    int k = blockIdx.x, c = threadIdx.x, lane = c & 31, w = c >> 5;
    int off = g_off[k], cnt = g_cnt[k];
    float acc = 0.0f;
    for (int i = 0; i < cnt; ++i) {
        int n = g_rows[off + i];
        acc += g_Zr[(size_t)n * DIMV + c];
    }
    float newe = (0.99f * ema_es[k * DIMV + c] + 0.01f * acc) * g_invc[k];
    g_newembed[k * DIMV + c] = newe;
    float part = (float)cnt * newe * newe - 2.0f * acc * newe;
    #pragma unroll
    for (int o = 16; o; o >>= 1) part += __shfl_xor_sync(0xFFFFFFFFu, part, o);
    if (lane == 0) ws[w] = part;
    __syncthreads();
    if (c == 0) {
        float s = 0;
        #pragma unroll
        for (int i = 0; i < 8; ++i) s += ws[i];
        atomicAdd(&g_l2, s);
    }
}

// ---------------- k_gather: write z_q (transposed), indices, loss ----------------
__global__ void k_gather(float* __restrict__ out) {
    __shared__ float stg[DIMV * 33];
    __shared__ int sk[32];
    int t = threadIdx.x;
    int n0 = blockIdx.x * 32;
    int b = n0 >> 14, s0 = n0 & (SPAT - 1);
    if (t < 32) {
        int k = g_idx[n0 + t];
        sk[t] = k;
        out[NTOT + 1 + n0 + t] = (float)k;
    }
    __syncthreads();
    #pragma unroll 4
    for (int i = 0; i < 32; ++i)
        stg[t * 33 + i] = g_newembed[sk[i] * DIMV + t];
    __syncthreads();
    float* ob = out + (size_t)b * (DIMV * SPAT) + s0;
    #pragma unroll 4
    for (int i = 0; i < 32; ++i) {
        int j = t + 256 * i;
        int c = j >> 5, r = j & 31;
        ob[(size_t)c * SPAT + r] = stg[c * 33 + r];
    }
    if (blockIdx.x == 0 && t == 0)
        out[NTOT] = 0.25f * (g_zsq + g_l2) * (1.0f / 16777216.0f);
}

// ---------------- launch ----------------
extern "C" void kernel_launch(void* const* d_in, const int* in_sizes, int n_in,
                              void* d_out, int out_size) {
    const float* z      = (const float*)d_in[0];
    const float* embed  = (const float*)d_in[1];
    const float* ema_cs = (const float*)d_in[2];
    const float* ema_es = (const float*)d_in[3];
    float* out = (float*)d_out;

    static bool init = false;
    if (!init) {
        cudaFuncSetAttribute(k_mma, cudaFuncAttributeMaxDynamicSharedMemorySize, SM_SZ2);
        init = true;
    }

    k_prep<<<KCODES, 256>>>(embed);
    k_split<<<dim3(512, 8, 4), 256>>>(z);
    k_dummy<<<1, 32>>>();
    k_mma<<<1024, 256, SM_SZ2>>>();
    k_rescore<<<8192, 256>>>(embed);
    k_scan<<<1, 1024>>>(ema_cs);
    k_bucket<<<256, 256>>>();
    k_esum<<<KCODES, 256>>>(ema_es);
    k_gather<<<2048, 256>>>(out);
}

// round 17
// speedup vs baseline: 1.1679x; 1.0362x over previous
#include <cuda_runtime.h>
#include <cuda_bf16.h>
#include <cstdint>
#include <math_constants.h>

// ---------------- problem constants ----------------
#define NQ      65536
#define DIMV    256
#define KCODES  1024
#define SPAT    16384
#define NTOT    16777216

// ---------------- device scratch ----------------
__device__ __nv_bfloat16 g_A[(size_t)NQ * 256];     // z_hi only (screening GEMM input)
__device__ float g_Zr[(size_t)NQ * DIMV];           // row-major fp32 z (exact)
__device__ __nv_bfloat16 g_E[KCODES * 256];         // e_hi
__device__ float g_heq2[KCODES];
__device__ int   g_cand[NQ * 8];                    // top-8 candidate codes per row
__device__ float g_cval[NQ * 8];                    // approx scores; [1]=+INF marks decided
__device__ int   g_idx[NQ];
__device__ int   g_cnt[KCODES];
__device__ int   g_off[KCODES];
__device__ int   g_cur[KCODES];
__device__ int   g_rows[NQ];
__device__ float g_invc[KCODES];
__device__ float g_newembed[KCODES * DIMV];
__device__ float g_zsq;
__device__ float g_l2;

// ---------------- PTX helpers (base sm_100 legal) ----------------
__device__ __forceinline__ uint32_t smem_u32(const void* p) {
    uint32_t a;
    asm("{ .reg .u64 t; cvta.to.shared.u64 t, %1; cvt.u32.u64 %0, t; }" : "=r"(a) : "l"(p));
    return a;
}
#define SWZ(x) ((x) ^ (((x) >> 3) & 0x70))

__device__ __forceinline__ void cpasync16(uint32_t s, const void* g) {
    asm volatile("cp.async.cg.shared.global [%0], [%1], 16;" :: "r"(s), "l"(g));
}
__device__ __forceinline__ void cpcommit() { asm volatile("cp.async.commit_group;"); }
__device__ __forceinline__ void cpwait0()  { asm volatile("cp.async.wait_group 0;" ::: "memory"); }

__device__ __forceinline__ void ldsm4(uint32_t* r, uint32_t a) {
    asm volatile("ldmatrix.sync.aligned.m8n8.x4.shared.b16 {%0,%1,%2,%3}, [%4];"
        : "=r"(r[0]), "=r"(r[1]), "=r"(r[2]), "=r"(r[3]) : "r"(a));
}
__device__ __forceinline__ void mma16816(float* c, const uint32_t* a, uint32_t b0, uint32_t b1) {
    asm volatile("mma.sync.aligned.m16n8k16.row.col.f32.bf16.bf16.f32 "
        "{%0,%1,%2,%3}, {%4,%5,%6,%7}, {%8,%9}, {%0,%1,%2,%3};"
        : "+f"(c[0]), "+f"(c[1]), "+f"(c[2]), "+f"(c[3])
        : "r"(a[0]), "r"(a[1]), "r"(a[2]), "r"(a[3]), "r"(b0), "r"(b1));
}

// sorted-desc top-4 insertion
__device__ __forceinline__ void ins4(float* tv, int* ti, float v, int c) {
    if (v <= tv[3]) return;
    if (v > tv[0]) {
        tv[3]=tv[2]; ti[3]=ti[2]; tv[2]=tv[1]; ti[2]=ti[1];
        tv[1]=tv[0]; ti[1]=ti[0]; tv[0]=v; ti[0]=c;
    } else if (v > tv[1]) {
        tv[3]=tv[2]; ti[3]=ti[2]; tv[2]=tv[1]; ti[2]=ti[1]; tv[1]=v; ti[1]=c;
    } else if (v > tv[2]) {
        tv[3]=tv[2]; ti[3]=ti[2]; tv[2]=v; ti[2]=c;
    } else { tv[3]=v; ti[3]=c; }
}
// sorted-desc top-8 insertion (bubble)
__device__ __forceinline__ void ins8(float* bv, int* bi, float v, int c) {
    if (v <= bv[7]) return;
    bv[7] = v; bi[7] = c;
    #pragma unroll
    for (int j = 7; j > 0; --j) {
        if (bv[j] > bv[j-1]) {
            float tf = bv[j]; bv[j] = bv[j-1]; bv[j-1] = tf;
            int   ii = bi[j]; bi[j] = bi[j-1]; bi[j-1] = ii;
        } else break;
    }
}

// ---------------- k_prep: build E (e_hi), heq2, zero counters ----------------
__global__ void k_prep(const float* __restrict__ embed) {
    __shared__ float ws[8];
    int k = blockIdx.x, c = threadIdx.x, lane = c & 31, w = c >> 5;
    float e = embed[k * DIMV + c];
    g_E[k * 256 + c] = __float2bfloat16(e);
    float s = e * e;
    #pragma unroll
    for (int o = 16; o; o >>= 1) s += __shfl_xor_sync(0xFFFFFFFFu, s, o);
    if (lane == 0) ws[w] = s;
    __syncthreads();
    if (c == 0) {
        float t = 0;
        #pragma unroll
        for (int i = 0; i < 8; ++i) t += ws[i];
        g_heq2[k] = 0.5f * t;
        g_cnt[k] = 0;
        if (k == 0) { g_zsq = 0.0f; g_l2 = 0.0f; }
    }
}

// ---------------- k_split: transpose z -> bf16 hi + fp32 row copy + sum(z^2) ----------------
__global__ void k_split(const float* __restrict__ z) {
    __shared__ float tile[32][33];
    __shared__ float ws[8];
    int s0 = blockIdx.x * 32, c0 = blockIdx.y * 32, b = blockIdx.z;
    int t = threadIdx.x, lane = t & 31, w = t >> 5;
    const float* zb = z + ((size_t)b * DIMV + c0) * SPAT + s0;
    float zsq = 0.0f;
    int si = t & 31, cb = t >> 5;
    #pragma unroll
    for (int i = 0; i < 4; ++i) {
        int c = cb + 8 * i;
        float v = zb[(size_t)c * SPAT + si];
        tile[c][si] = v;
        zsq += v * v;
    }
    __syncthreads();
    int ci = t & 31, rb = t >> 5;
    #pragma unroll
    for (int i = 0; i < 4; ++i) {
        int r = rb + 8 * i;
        float v = tile[ci][r];
        size_t n = (size_t)b * SPAT + s0 + r;
        g_A[n * 256 + c0 + ci] = __float2bfloat16(v);
        g_Zr[n * DIMV + c0 + ci] = v;
    }
    #pragma unroll
    for (int o = 16; o; o >>= 1) zsq += __shfl_xor_sync(0xFFFFFFFFu, zsq, o);
    if (lane == 0) ws[w] = zsq;
    __syncthreads();
    if (t == 0) {
        float s = 0;
        #pragma unroll
        for (int i = 0; i < 8; ++i) s += ws[i];
        atomicAdd(&g_zsq, s);
    }
}

// ---------------- k_dummy: spacer so k_mma is the 4th launch (ncu capture slot) ----------------
__global__ void k_dummy() {}

// ---------------- k_mma: K=256 HMMA screen, M=64, 2-buffer ring, 3 CTAs/SM ----------------
#define SM_A    0                       // 4 chunks x 8192 = 32768
#define SM_B    32768                   // 2 x 16384 = 32768 -> 65536
#define SM_HQ   65536                   // 4096 -> 69632
#define SM_END  69632
#define SM_SZ2  (SM_END + 1024)
// staging scv/sci overlays the B ring after the mainloop (16 KB needed, 32 KB available)

__global__ __launch_bounds__(256, 3) void k_mma() {
    extern __shared__ char smraw[];
    uint32_t base0 = smem_u32(smraw);
    uint32_t sb = (base0 + 1023u) & ~1023u;
    char* sp = smraw + (sb - base0);
    const uint32_t A = sb + SM_A, B = sb + SM_B;
    float* heqs = (float*)(sp + SM_HQ);
    float* scv  = (float*)(sp + SM_B);           // overlay (post-mainloop)
    int*   sci  = (int*)(sp + SM_B + 8192);      // overlay (post-mainloop)

    const int t = threadIdx.x, lane = t & 31, w = t >> 5;
    const int warp_m = w >> 1, warp_n = w & 1;   // 4 x 16 rows, 2 x 64 cols
    const int n0 = blockIdx.x * 64;

    #pragma unroll
    for (int i = 0; i < 4; ++i) heqs[t + 256 * i] = g_heq2[t + 256 * i];

    // per-thread cp.async offsets for a [128][64] B chunk (computed once)
    uint32_t sm_off[4], gl_off[4];
    #pragma unroll
    for (int j = 0; j < 4; ++j) {
        int seg = t + 256 * j;          // 1024 16B segments
        int r = seg >> 3, g8 = seg & 7;
        sm_off[j] = SWZ((uint32_t)(r * 128 + g8 * 16));
        gl_off[j] = (uint32_t)(r * 256 + g8 * 8);   // elements
    }

    // A tile: 64 rows x 256 bf16 as 4 chunks [64][64] (8KB each), SW128-swizzled
    const __nv_bfloat16* Ag = g_A + (size_t)n0 * 256;
    #pragma unroll
    for (int j = 0; j < 8; ++j) {
        int i = t + 256 * j;            // 2048 16B segments
        int r = i >> 5, g = i & 31;
        int chunk = g >> 3, g8 = g & 7;
        cpasync16(A + chunk * 8192 + SWZ(r * 128 + g8 * 16), Ag + (size_t)r * 256 + g * 8);
    }
    cpcommit();
    // B prologue: chunk 0 into buffer 0 (prefetch distance 1, 2 buffers)
    {
        const __nv_bfloat16* Eg = g_E;
        #pragma unroll
        for (int j = 0; j < 4; ++j)
            cpasync16(B + sm_off[j], Eg + gl_off[j]);
        cpcommit();
    }

    // LDSM offsets (chunk/buffer-relative, loop-invariant; lean register footprint)
    uint32_t a_off[4];
    {
        int ar = warp_m * 16 + (lane & 15);
        uint32_t asw = (uint32_t)((ar & 7) << 4);
        #pragma unroll
        for (int ks = 0; ks < 4; ++ks)
            a_off[ks] = (uint32_t)(ar * 128)
                      + (((uint32_t)(ks * 32 + ((lane >> 4) * 16))) ^ asw);
    }
    const int sel = lane >> 3;
    uint32_t b_off[4][4];
    #pragma unroll
    for (int ntp = 0; ntp < 4; ++ntp) {
        int brow = warp_n * 64 + ntp * 16 + (sel >> 1) * 8 + (lane & 7);
        #pragma unroll
        for (int ks = 0; ks < 4; ++ks)
            b_off[ntp][ks] = (uint32_t)(brow * 128)
                           + (((uint32_t)(ks * 32 + (sel & 1) * 16)) ^ ((uint32_t)((brow & 7) << 4)));
    }

    float acc[8][4];                     // warp tile 16 x 64
    float tv[2][4];
    int   ti[2][4];
    #pragma unroll
    for (int s = 0; s < 2; ++s)
        #pragma unroll
        for (int j = 0; j < 4; ++j) { tv[s][j] = -CUDART_INF_F; ti[s][j] = 0; }

    for (int g = 0; g < 32; ++g) {
        const int nt = g >> 2, h = g & 3;
        cpwait0();                      // A + B chunks 0..g complete
        __syncthreads();

        // prefetch chunk g+1 into buffer (g+1)&1 (consumed at g-1; safe after sync)
        if (g + 1 < 32) {
            int gn = g + 1;
            const __nv_bfloat16* Eg = g_E + (size_t)((gn >> 2) * 128) * 256 + (gn & 3) * 64;
            uint32_t bb = B + (gn & 1) * 16384;
            #pragma unroll
            for (int j = 0; j < 4; ++j)
                cpasync16(bb + sm_off[j], Eg + gl_off[j]);
        }
        cpcommit();

        if (h == 0) {
            #pragma unroll
            for (int nti = 0; nti < 8; ++nti)
                #pragma unroll
                for (int q = 0; q < 4; ++q) acc[nti][q] = 0.0f;
        }

        // gemm: A chunk h, B buffer g&1
        {
            const uint32_t Ab = A + h * 8192;
            const uint32_t Bb = B + (g & 1) * 16384;
            #pragma unroll
            for (int ks = 0; ks < 4; ++ks) {
                uint32_t af[4];
                ldsm4(af, Ab + a_off[ks]);
                uint32_t bfg[4][4];
                #pragma unroll
                for (int ntp = 0; ntp < 4; ++ntp)
                    ldsm4(bfg[ntp], Bb + b_off[ntp][ks]);
                #pragma unroll
                for (int nti = 0; nti < 8; ++nti) {
                    int ntp = nti >> 1, pr = (nti & 1) * 2;
                    mma16816(acc[nti], af, bfg[ntp][pr], bfg[ntp][pr + 1]);
                }
            }
        }

        if (h == 3) {
            #pragma unroll
            for (int nti = 0; nti < 8; ++nti) {
                int code0 = nt * 128 + warp_n * 64 + nti * 8 + 2 * (lane & 3);
                float h0 = heqs[code0], h1 = heqs[code0 + 1];
                ins4(tv[0], ti[0], acc[nti][0] - h0, code0);
                ins4(tv[0], ti[0], acc[nti][1] - h1, code0 + 1);
                ins4(tv[1], ti[1], acc[nti][2] - h0, code0);
                ins4(tv[1], ti[1], acc[nti][3] - h1, code0 + 1);
            }
        }
    }

    // all B reads done; overlay staging onto the B ring
    __syncthreads();
    #pragma unroll
    for (int s = 0; s < 2; ++s) {
        int row = warp_m * 16 + s * 8 + (lane >> 2);
        int col = warp_n * 16 + (lane & 3) * 4;
        #pragma unroll
        for (int j = 0; j < 4; ++j) {
            scv[row * 32 + col + j] = tv[s][j];
            sci[row * 32 + col + j] = ti[s][j];
        }
    }
    __syncthreads();
    if (t < 64) {
        float bv[8]; int bi[8];
        #pragma unroll
        for (int j = 0; j < 8; ++j) { bv[j] = -CUDART_INF_F; bi[j] = 0; }
        #pragma unroll 4
        for (int i = 0; i < 32; ++i) ins8(bv, bi, scv[t * 32 + i], sci[t * 32 + i]);
        size_t base = (size_t)(n0 + t) * 8;
        if (bv[0] - bv[1] >= 0.03f) {
            g_idx[n0 + t] = bi[0];
            atomicAdd(&g_cnt[bi[0]], 1);
            g_cand[base] = bi[0];
            g_cval[base] = bv[0];
            g_cval[base + 1] = __int_as_float(0x7f800000);   // +INF = decided marker
        } else {
            #pragma unroll
            for (int j = 0; j < 8; ++j) {
                g_cand[base + j] = bi[j];
                g_cval[base + j] = bv[j];
            }
        }
    }
}

// ---------------- k_rescore: skip decided rows; gated exact fp32 + fp64 verify ----------------
__global__ __launch_bounds__(256) void k_rescore(const float* __restrict__ embed) {
    int t = threadIdx.x, lane = t & 31, w = t >> 5;
    int r = blockIdx.x * 8 + w;

    float cv1 = g_cval[(size_t)r * 8 + 1];
    if (cv1 == __int_as_float(0x7f800000)) return;

    const float4* zp = (const float4*)(g_Zr + (size_t)r * DIMV + lane * 8);
    float4 z0 = zp[0], z1 = zp[1];
    float zv[8] = { z0.x, z0.y, z0.z, z0.w, z1.x, z1.y, z1.z, z1.w };

    int   ck[8];
    float cv[8];
    #pragma unroll
    for (int j = 0; j < 8; ++j) {
        ck[j] = g_cand[(size_t)r * 8 + j];
        cv[j] = g_cval[(size_t)r * 8 + j];
    }
    const float thr = cv[0] - 0.01f;

    float best = -CUDART_INF_F, second = -CUDART_INF_F;
    int bidx = 0x7FFFFFFF;
    float sc[8];
    #pragma unroll
    for (int c = 0; c < 8; ++c) sc[c] = -CUDART_INF_F;

    for (int c = 0; c < 8; ++c) {
        if (cv[c] < thr) break;
        int k = ck[c];
        const float4* ep = (const float4*)(embed + (size_t)k * DIMV + lane * 8);
        float4 e0 = ep[0], e1 = ep[1];
        float p = zv[0] * e0.x + zv[1] * e0.y + zv[2] * e0.z + zv[3] * e0.w
                + zv[4] * e1.x + zv[5] * e1.y + zv[6] * e1.z + zv[7] * e1.w;
        #pragma unroll
        for (int o = 16; o; o >>= 1) p += __shfl_xor_sync(0xFFFFFFFFu, p, o);
        float s = p - g_heq2[k];
        sc[c] = s;
        if (s > best || (s == best && k < bidx)) { second = best; best = s; bidx = k; }
        else if (s > second) second = s;
    }

    if (best - second < 1e-3f) {
        double dbest = -CUDART_INF;
        int dbidx = 0x7FFFFFFF;
        for (int c = 0; c < 8; ++c) {
            if (sc[c] < best - 2e-3f) continue;
            int k = ck[c];
            const float4* ep = (const float4*)(embed + (size_t)k * DIMV + lane * 8);
            float4 e0 = ep[0], e1 = ep[1];
            double acc = 0.0, e2 = 0.0;
            double ev[8] = { e0.x, e0.y, e0.z, e0.w, e1.x, e1.y, e1.z, e1.w };
            #pragma unroll
            for (int j = 0; j < 8; ++j) {
                acc += (double)zv[j] * ev[j];
                e2  += ev[j] * ev[j];
            }
            double s2 = acc - 0.5 * e2;
            #pragma unroll
            for (int o = 16; o; o >>= 1) s2 += __shfl_xor_sync(0xFFFFFFFFu, s2, o);
            if (s2 > dbest || (s2 == dbest && k < dbidx)) { dbest = s2; dbidx = k; }
        }
        bidx = dbidx;
    }

    if (lane == 0) {
        g_idx[r] = bidx;
        atomicAdd(&g_cnt[bidx], 1);
    }
}

// ---------------- k_scan: EMA sizes + invc + exclusive prefix of counts ----------------
__global__ void k_scan(const float* __restrict__ ema_cs) {
    __shared__ float red[KCODES];
    __shared__ int sc[KCODES];
    int t = threadIdx.x;
    int c = g_cnt[t];
    float ncs = 0.99f * ema_cs[t] + 0.01f * (float)c;
    red[t] = ncs; sc[t] = c;
    __syncthreads();
    for (int s = 512; s > 0; s >>= 1) { if (t < s) red[t] += red[t + s]; __syncthreads(); }
    float n = red[0];
    for (int off = 1; off < KCODES; off <<= 1) {
        int v = (t >= off) ? sc[t - off] : 0;
        __syncthreads();
        sc[t] += v;
        __syncthreads();
    }
    int excl = sc[t] - c;
    g_off[t] = excl; g_cur[t] = excl;
    float cl = (ncs + 1e-5f) / (n + KCODES * 1e-5f) * n;
    g_invc[t] = 1.0f / cl;
}

// ---------------- k_bucket ----------------
__global__ void k_bucket() {
    int n = blockIdx.x * 256 + threadIdx.x;
    int k = g_idx[n];
    int p = atomicAdd(&g_cur[k], 1);
    g_rows[p] = n;
}

// ---------------- k_esum: per-code fp32 sum + new codebook + loss terms ----------------
__global__ void k_esum(const float* __restrict__ ema_es) {
    __shared__ float ws[8];
    int k = blockIdx.x, c = threadIdx.x, lane = c & 31, w = c >> 5;
    int off = g_off[k], cnt = g_cnt[k];
    float acc = 0.0f;
    for (int i = 0; i < cnt; ++i) {
        int n = g_rows[off + i];
        acc += g_Zr[(size_t)n * DIMV + c];
    }
    float newe = (0.99f * ema_es[k * DIMV + c] + 0.01f * acc) * g_invc[k];
    g_newembed[k * DIMV + c] = newe;
    float part = (float)cnt * newe * newe - 2.0f * acc * newe;
    #pragma unroll
    for (int o = 16; o; o >>= 1) part += __shfl_xor_sync(0xFFFFFFFFu, part, o);
    if (lane == 0) ws[w] = part;
    __syncthreads();
    if (c == 0) {
        float s = 0;
        #pragma unroll
        for (int i = 0; i < 8; ++i) s += ws[i];
        atomicAdd(&g_l2, s);
    }
}

// ---------------- k_gather: write z_q (transposed), indices, loss ----------------
__global__ void k_gather(float* __restrict__ out) {
    __shared__ float stg[DIMV * 33];
    __shared__ int sk[32];
    int t = threadIdx.x;
    int n0 = blockIdx.x * 32;
    int b = n0 >> 14, s0 = n0 & (SPAT - 1);
    if (t < 32) {
        int k = g_idx[n0 + t];
        sk[t] = k;
        out[NTOT + 1 + n0 + t] = (float)k;
    }
    __syncthreads();
    #pragma unroll 4
    for (int i = 0; i < 32; ++i)
        stg[t * 33 + i] = g_newembed[sk[i] * DIMV + t];
    __syncthreads();
    float* ob = out + (size_t)b * (DIMV * SPAT) + s0;
    #pragma unroll 4
    for (int i = 0; i < 32; ++i) {
        int j = t + 256 * i;
        int c = j >> 5, r = j & 31;
        ob[(size_t)c * SPAT + r] = stg[c * 33 + r];
    }
    if (blockIdx.x == 0 && t == 0)
        out[NTOT] = 0.25f * (g_zsq + g_l2) * (1.0f / 16777216.0f);
}

// ---------------- launch ----------------
extern "C" void kernel_launch(void* const* d_in, const int* in_sizes, int n_in,
                              void* d_out, int out_size) {
    const float* z      = (const float*)d_in[0];
    const float* embed  = (const float*)d_in[1];
    const float* ema_cs = (const float*)d_in[2];
    const float* ema_es = (const float*)d_in[3];
    float* out = (float*)d_out;

    static bool init = false;
    if (!init) {
        cudaFuncSetAttribute(k_mma, cudaFuncAttributeMaxDynamicSharedMemorySize, SM_SZ2);
        init = true;
    }

    k_prep<<<KCODES, 256>>>(embed);
    k_split<<<dim3(512, 8, 4), 256>>>(z);
    k_dummy<<<1, 32>>>();
    k_mma<<<1024, 256, SM_SZ2>>>();
    k_rescore<<<8192, 256>>>(embed);
    k_scan<<<1, 1024>>>(ema_cs);
    k_bucket<<<256, 256>>>();
    k_esum<<<KCODES, 256>>>(ema_es);
    k_gather<<<2048, 256>>>(out);
}